// round 2
// baseline (speedup 1.0000x reference)
#include <cuda_runtime.h>
#include <math.h>

#define VOCAB   128000
#define NVEC    (VOCAB / 4)
#define TOPK    50
#define TOPP    0.9f
#define NEGV    (-1000000000.0f)
#define NBINS   4096
#define NCHUNK  (NBINS / 32)
#define CAP     4096
#define NT      1024
#define SSTRIDE 64
#define NSAMP   (VOCAB / SSTRIDE)   // 2000 samples per row
#define SCUM    8u                  // sample count target above threshold

__device__ __forceinline__ unsigned int fkey(float f) {
    unsigned int u = __float_as_uint(f);
    // monotonic key: ascending key order == ascending float order
    return (u & 0x80000000u) ? ~u : (u | 0x80000000u);
}
__device__ __forceinline__ float unkey(unsigned int k) {
    return __uint_as_float((k & 0x80000000u) ? (k & 0x7FFFFFFFu) : ~k);
}

__global__ __launch_bounds__(NT)
void topk_topp_kernel(const float* __restrict__ logits, float* __restrict__ out) {
    __shared__ unsigned int hist[NBINS];
    __shared__ unsigned int chunkSum[NCHUNK];
    __shared__ unsigned long long buf[CAP];   // (key<<32) | (0xFFFFFFFF - idx)
    __shared__ unsigned int s_cnt;
    __shared__ unsigned int s_thr;
    __shared__ unsigned int s_cntAbove;
    __shared__ int s_needRefine;
    __shared__ int s_m;

    const int row = blockIdx.x;
    const float* rp = logits + (size_t)row * VOCAB;
    const float4* rp4 = (const float4*)rp;
    float4* op4 = (float4*)(out + (size_t)row * VOCAB);
    const int tid = threadIdx.x;

    // ---------------- phase 0: sampled threshold estimate ----------------
    for (int i = tid; i < NBINS; i += NT) hist[i] = 0u;
    if (tid == 0) s_cnt = 0u;
    __syncthreads();
    for (int t = tid; t < NSAMP; t += NT)
        atomicAdd(&hist[fkey(rp[t * SSTRIDE]) >> 20], 1u);
    __syncthreads();
    if (tid < NCHUNK) {
        unsigned int s = 0;
        #pragma unroll 8
        for (int j = 0; j < 32; j++) s += hist[tid * 32 + j];
        chunkSum[tid] = s;
    }
    __syncthreads();
    if (tid == 0) {
        unsigned int cum = 0; int b = 0;
        for (int c = NCHUNK - 1; c >= 0; c--) {
            if (cum + chunkSum[c] >= SCUM) {
                for (int j = 31; j >= 0; j--) {
                    int bin = c * 32 + j; cum += hist[bin];
                    if (cum >= SCUM) { b = bin; break; }
                }
                break;
            }
            cum += chunkSum[c];
        }
        s_thr = ((unsigned int)b) << 20;
    }
    __syncthreads();

    // ------- phase 1: fused single pass: NEG-fill output + collect candidates -------
    {
        const unsigned int T = s_thr;
        const float4 neg4 = make_float4(NEGV, NEGV, NEGV, NEGV);
        for (int i = tid; i < NVEC; i += NT) {
            float4 v = rp4[i];
            op4[i] = neg4;
            unsigned int k0 = fkey(v.x), k1 = fkey(v.y), k2 = fkey(v.z), k3 = fkey(v.w);
            unsigned int g = (unsigned int)(i * 4);
            if (k0 >= T) { unsigned p = atomicAdd(&s_cnt, 1u); if (p < CAP) buf[p] = ((unsigned long long)k0 << 32) | (unsigned long long)(0xFFFFFFFFu - g); }
            if (k1 >= T) { unsigned p = atomicAdd(&s_cnt, 1u); if (p < CAP) buf[p] = ((unsigned long long)k1 << 32) | (unsigned long long)(0xFFFFFFFFu - (g + 1u)); }
            if (k2 >= T) { unsigned p = atomicAdd(&s_cnt, 1u); if (p < CAP) buf[p] = ((unsigned long long)k2 << 32) | (unsigned long long)(0xFFFFFFFFu - (g + 2u)); }
            if (k3 >= T) { unsigned p = atomicAdd(&s_cnt, 1u); if (p < CAP) buf[p] = ((unsigned long long)k3 << 32) | (unsigned long long)(0xFFFFFFFFu - (g + 3u)); }
        }
    }
    __syncthreads();

    // ------- phase 1b: exact fallback if sampling mis-estimated (rare) -------
    if (s_cnt < (unsigned)TOPK || s_cnt > (unsigned)CAP) {
        for (int i = tid; i < NBINS; i += NT) hist[i] = 0u;
        __syncthreads();
        for (int i = tid; i < NVEC; i += NT) {
            float4 v = rp4[i];
            atomicAdd(&hist[fkey(v.x) >> 20], 1u);
            atomicAdd(&hist[fkey(v.y) >> 20], 1u);
            atomicAdd(&hist[fkey(v.z) >> 20], 1u);
            atomicAdd(&hist[fkey(v.w) >> 20], 1u);
        }
        __syncthreads();
        if (tid < NCHUNK) {
            unsigned int s = 0;
            #pragma unroll 8
            for (int j = 0; j < 32; j++) s += hist[tid * 32 + j];
            chunkSum[tid] = s;
        }
        __syncthreads();
        if (tid == 0) {
            unsigned int cum = 0; int b = 0;
            for (int c = NCHUNK - 1; c >= 0; c--) {
                if (cum + chunkSum[c] >= (unsigned)TOPK) {
                    for (int j = 31; j >= 0; j--) {
                        int bin = c * 32 + j; cum += hist[bin];
                        if (cum >= (unsigned)TOPK) { b = bin; break; }
                    }
                    break;
                }
                cum += chunkSum[c];
            }
            s_cntAbove = cum - hist[b];
            s_needRefine = (cum > (unsigned)CAP) ? 1 : 0;
            s_thr = ((unsigned int)b) << 20;
            s_cnt = 0u;
        }
        __syncthreads();
        if (s_needRefine) {
            const unsigned int bb = s_thr >> 20;
            const unsigned int above = s_cntAbove;
            for (int i = tid; i < NBINS; i += NT) hist[i] = 0u;
            __syncthreads();
            for (int i = tid; i < NVEC; i += NT) {
                float4 v = rp4[i];
                unsigned int k0 = fkey(v.x), k1 = fkey(v.y), k2 = fkey(v.z), k3 = fkey(v.w);
                if ((k0 >> 20) == bb) atomicAdd(&hist[(k0 >> 8) & 0xFFFu], 1u);
                if ((k1 >> 20) == bb) atomicAdd(&hist[(k1 >> 8) & 0xFFFu], 1u);
                if ((k2 >> 20) == bb) atomicAdd(&hist[(k2 >> 8) & 0xFFFu], 1u);
                if ((k3 >> 20) == bb) atomicAdd(&hist[(k3 >> 8) & 0xFFFu], 1u);
            }
            __syncthreads();
            if (tid < NCHUNK) {
                unsigned int s = 0;
                #pragma unroll 8
                for (int j = 0; j < 32; j++) s += hist[tid * 32 + j];
                chunkSum[tid] = s;
            }
            __syncthreads();
            if (tid == 0) {
                unsigned int cum = above; int b2 = 0;
                for (int c = NCHUNK - 1; c >= 0; c--) {
                    if (cum + chunkSum[c] >= (unsigned)TOPK) {
                        for (int j = 31; j >= 0; j--) {
                            int bin = c * 32 + j; cum += hist[bin];
                            if (cum >= (unsigned)TOPK) { b2 = bin; break; }
                        }
                        break;
                    }
                    cum += chunkSum[c];
                }
                s_thr = (bb << 20) | (((unsigned int)b2) << 8);
                s_cnt = 0u;
            }
            __syncthreads();
        }
        // re-collect with exact threshold
        {
            const unsigned int T = s_thr;
            for (int i = tid; i < NVEC; i += NT) {
                float4 v = rp4[i];
                unsigned int k[4] = {fkey(v.x), fkey(v.y), fkey(v.z), fkey(v.w)};
                unsigned int g = (unsigned int)(i * 4);
                #pragma unroll
                for (int c = 0; c < 4; c++) {
                    if (k[c] >= T) {
                        unsigned p = atomicAdd(&s_cnt, 1u);
                        if (p < CAP) buf[p] = ((unsigned long long)k[c] << 32) | (unsigned long long)(0xFFFFFFFFu - (g + (unsigned)c));
                    }
                }
            }
        }
        __syncthreads();
    }

    // ---------------- phase 2: sort candidates (desc value, asc index) ----------------
    int C = (int)min(s_cnt, (unsigned)CAP);
    int N2 = 64; while (N2 < C) N2 <<= 1;
    for (int i = C + tid; i < N2; i += NT) buf[i] = 0ULL;
    __syncthreads();
    for (unsigned int k = 2; k <= (unsigned)N2; k <<= 1) {
        for (unsigned int j = k >> 1; j > 0; j >>= 1) {
            for (unsigned int i = tid; i < (unsigned)N2; i += NT) {
                unsigned int ixj = i ^ j;
                if (ixj > i) {
                    unsigned long long a = buf[i], c = buf[ixj];
                    bool up = ((i & k) == 0u);   // descending blocks
                    if (up ? (a < c) : (a > c)) { buf[i] = c; buf[ixj] = a; }
                }
            }
            __syncthreads();
        }
    }

    // ---------------- phase 3: top-p over sorted top-50 ----------------
    if (tid == 0) {
        int kk = (C < TOPK) ? C : TOPK;
        float vmax = unkey((unsigned int)(buf[0] >> 32));
        float e[TOPK];
        float s = 0.0f;
        for (int i = 0; i < kk; i++) {
            e[i] = expf(unkey((unsigned int)(buf[i] >> 32)) - vmax);
            s += e[i];
        }
        float cum = 0.0f;
        int m = kk;
        for (int i = 0; i < kk; i++) {
            cum += e[i] / s;
            if (cum > TOPP) { m = i + 1; break; }
        }
        s_m = m;
    }
    __syncthreads();

    // ---------------- phase 4: scatter kept values ----------------
    if (tid < s_m) {
        unsigned long long b = buf[tid];
        unsigned int g = 0xFFFFFFFFu - (unsigned int)(b & 0xFFFFFFFFu);
        out[(size_t)row * VOCAB + g] = unkey((unsigned int)(b >> 32));
    }
}

extern "C" void kernel_launch(void* const* d_in, const int* in_sizes, int n_in,
                              void* d_out, int out_size) {
    const float* logits = (const float*)d_in[0];
    float* out = (float*)d_out;
    int rows = in_sizes[0] / VOCAB;          // 32*8 = 256
    topk_topp_kernel<<<rows, NT>>>(logits, out);
}